// round 11
// baseline (speedup 1.0000x reference)
#include <cuda_runtime.h>
#include <cstdint>

#define NEGF (-1e30f)
#define EPSF (1e-7f)
#define LN2F (0.69314718055994531f)

constexpr int Bc = 64;
constexpr int Tc = 1024;
constexpr int Cc = 128;
constexpr int Lc = 256;
constexpr int Sc = 2 * Lc + 1;   // 513
constexpr int BLANKc = Cc - 1;   // 127
constexpr int NT = 128;

__device__ float g_alpha[Bc][Sc];
__device__ float g_gamma[Bc][Sc];
__device__ int   g_done[Bc];     // zero-initialized; reset to 0 by the combiner each launch

__device__ __forceinline__ float ex2f_(float x){ float r; asm("ex2.approx.ftz.f32 %0, %1;" : "=f"(r) : "f"(x)); return r; }
__device__ __forceinline__ float lg2f_(float x){ float r; asm("lg2.approx.f32 %0, %1;"    : "=f"(r) : "f"(x)); return r; }

__device__ __forceinline__ float lse2f(float a, float b){
    float m = fmaxf(a, b), l = fminf(a, b);
    return m + lg2f_(1.0f + ex2f_(l - m));
}
__device__ __forceinline__ float lse3f(float x, float y, float z){
    float hi = fmaxf(x, y), lo = fminf(x, y);
    float m  = fmaxf(hi, z), t1 = fminf(hi, z);
    float mid = fmaxf(t1, lo), low = fminf(t1, lo);
    return m + lg2f_(1.0f + ex2f_(mid - m) + ex2f_(low - m));
}

// ---------------- forward 2-step block (states: 4*tid .. 4*tid+3, +512 on last) ----------------
#define FWD_BODY(J, S1, S2, S3, S4, ACT1, ACT2) do {                                   \
    lpS[S3][tid] = lg2f_(pA0 + EPSF);                                                   \
    lpS[S4][tid] = lg2f_(pA1 + EPSF);                                                   \
    pA0 = pB0; pA1 = pB1; pB0 = pC0; pB1 = pC1;                                         \
    pC0 = yp[(size_t)(2*(J)+ 9) * Cc + tid];                                            \
    pC1 = yp[(size_t)(2*(J)+10) * Cc + tid];                                            \
    float4 hB = halo[(J)&1][tid+1];                                                     \
    const float lb1 = lpS[S1][BLANKc], lb2 = lpS[S2][BLANKc];                           \
    float n1 = lse3f(hB.w, hB.z, skp1 ? hB.y : NEGF) + lpS[S1][e1];                     \
    float n2 = lse2f(A0, hB.w) + lb1;                                                   \
    float n3 = lse3f(A1, A0, skp3 ? hB.w : NEGF) + lpS[S1][e3];                         \
    float n4 = lse2f(A2, A1) + lb1;                                                     \
    float n5 = lse3f(A3, A2, skp5 ? A1 : NEGF) + lpS[S1][e5];                           \
    float n6 = 0.f;                                                                     \
    if (isLast) n6 = (ACT1) ? (lse2f(A4, A3) + lb1) : A4;                               \
    if (!(ACT1)) { n1 = hB.w; n2 = A0; n3 = A1; n4 = A2; n5 = A3; }                     \
    float w0 = lse2f(n2, n1) + lb2;                                                     \
    float w1 = lse3f(n3, n2, skp3 ? n1 : NEGF) + lpS[S2][e3];                           \
    float w2 = lse2f(n4, n3) + lb2;                                                     \
    float w3 = lse3f(n5, n4, skp5 ? n3 : NEGF) + lpS[S2][e5];                           \
    if (ACT2) { A0 = w0; A1 = w1; A2 = w2; A3 = w3; }                                   \
    else      { A0 = n2; A1 = n3; A2 = n4; A3 = n5; }                                   \
    if (isLast) A4 = (ACT2) ? (lse2f(n6, n5) + lb2) : n6;                               \
    halo[((J)+1)&1][tid+2] = make_float4(A0, A1, A2, A3);                               \
    __syncthreads();                                                                    \
} while (0)

#define FWD_FINAL(S, ACT) do {                                                          \
    float4 hB = halo[255 & 1][tid+1];                                                   \
    const float lbf = lpS[S][BLANKc];                                                   \
    float w0 = lse2f(A0, hB.w) + lbf;                                                   \
    float w1 = lse3f(A1, A0, skp3 ? hB.w : NEGF) + lpS[S][e3];                          \
    float w2 = lse2f(A2, A1) + lbf;                                                     \
    float w3 = lse3f(A3, A2, skp5 ? A1 : NEGF) + lpS[S][e5];                            \
    float w4 = 0.f;                                                                     \
    if (isLast) w4 = lse2f(A4, A3) + lbf;                                               \
    if (ACT) { A0 = w0; A1 = w1; A2 = w2; A3 = w3; if (isLast) A4 = w4; }               \
} while (0)

// ---------------- backward 2-step block (states: 4*tid .. 4*tid+3, +512 on last) ----------------
#define BWD_BODY(J, S1, S2, S3, S4, ACT1, ACT2) do {                                    \
    lpS[S3][tid] = lg2f_(pA0 + EPSF);                                                   \
    lpS[S4][tid] = lg2f_(pA1 + EPSF);                                                   \
    pA0 = pB0; pA1 = pB1; pB0 = pC0; pB1 = pC1;                                         \
    pC0 = yp[(size_t)(1015 - 2*(J)) * Cc + tid];                                        \
    pC1 = yp[(size_t)(1014 - 2*(J)) * Cc + tid];                                        \
    float4 hU = halo[(J)&1][tid+1];                                                     \
    if (isLast) hU = make_float4(A2, NEGF, NEGF, NEGF);                                 \
    const float lb1 = lpS[S1][BLANKc], lb2 = lpS[S2][BLANKc];                           \
    float D0 = lb1 + g0;             float D1 = lpS[S1][eb1] + g1;                      \
    float D2 = lb1 + g2;             float D3 = lpS[S1][eb3] + g3;                      \
    float D4 = lb1 + hU.x;           float D5 = lpS[S1][eb5] + hU.y;                    \
    float D6 = lb1 + hU.z;           float D7 = lpS[S1][eb7] + hU.w;                    \
    float n0 = lse2f(D0, D1);                                                           \
    float n1 = lse3f(D1, D2, skbA ? D3 : NEGF);                                         \
    float n2 = lse2f(D2, D3);                                                           \
    float n3 = lse3f(D3, D4, skbB ? D5 : NEGF);                                         \
    float n4 = lse2f(D4, D5);                                                           \
    float n5 = lse3f(D5, D6, skbC ? D7 : NEGF);                                         \
    if (!(ACT1)) { n0 = g0; n1 = g1; n2 = g2; n3 = g3; n4 = hU.x; n5 = hU.y; }          \
    float E0 = lb2 + n0;             float E1 = lpS[S2][eb1] + n1;                      \
    float E2 = lb2 + n2;             float E3 = lpS[S2][eb3] + n3;                      \
    float E4 = lb2 + n4;             float E5 = lpS[S2][eb5] + n5;                      \
    float m0 = lse2f(E0, E1);                                                           \
    float m1 = lse3f(E1, E2, skbA ? E3 : NEGF);                                         \
    float m2 = lse2f(E2, E3);                                                           \
    float m3 = lse3f(E3, E4, skbB ? E5 : NEGF);                                         \
    if (ACT2) { g0 = m0; g1 = m1; g2 = m2; g3 = m3; }                                   \
    else      { g0 = n0; g1 = n1; g2 = n2; g3 = n3; }                                   \
    if (isLast) A2 = (ACT2) ? (lb2 + n4) : n4;                                          \
    halo[((J)+1)&1][tid] = make_float4(g0, g1, g2, g3);                                 \
    __syncthreads();                                                                    \
} while (0)

__global__ __launch_bounds__(NT, 1) void ctc_fb_kernel(
    const int*   __restrict__ y_true,        // (B, L)
    const float* __restrict__ y_pred,        // (B, T, C)
    const int*   __restrict__ input_length,  // (B, 1)
    const int*   __restrict__ label_length,  // (B, 1)
    float*       __restrict__ out)           // (B, 1)
{
    __shared__ float  lpS[4][Cc];
    __shared__ float4 halo[2][NT + 2];
    __shared__ float  warpRes[4];
    __shared__ int    ticket;

    const bool fwd = (blockIdx.x < Bc);
    const int b    = fwd ? blockIdx.x : (blockIdx.x - Bc);
    const int tid  = threadIdx.x;
    const bool isLast = (tid == NT - 1);
    const float* __restrict__ yp = y_pred + (size_t)b * Tc * Cc;
    const int*   __restrict__ yt = y_true + b * Lc;
    const int inLen  = input_length[b];
    const int labLen = label_length[b];

    if (fwd) {
        // per-thread label / skip tables for states 4t-1, 4t+1, 4t+3
        const int e1 = yt[max(2 * tid - 1, 0)];
        const int e3 = yt[2 * tid];
        const int e5 = yt[2 * tid + 1];
        const bool skp1 = (tid >= 1) && (e1 != yt[max(2 * tid - 2, 0)]);
        const bool skp3 = (tid >= 1) && (e3 != yt[max(2 * tid - 1, 0)]);
        const bool skp5 = (e5 != e3);

        float A0 = NEGF, A1 = NEGF, A2 = NEGF, A3 = NEGF, A4 = NEGF;
        if (tid == 0) {
            A0 = lg2f_(yp[BLANKc] + EPSF);
            if (labLen > 0) A1 = lg2f_(yp[yt[0]] + EPSF);
        }

        lpS[1][tid] = lg2f_(yp[(size_t)1 * Cc + tid] + EPSF);
        lpS[2][tid] = lg2f_(yp[(size_t)2 * Cc + tid] + EPSF);
        float pA0 = yp[(size_t)3 * Cc + tid], pA1 = yp[(size_t)4 * Cc + tid];
        float pB0 = yp[(size_t)5 * Cc + tid], pB1 = yp[(size_t)6 * Cc + tid];
        float pC0 = yp[(size_t)7 * Cc + tid], pC1 = yp[(size_t)8 * Cc + tid];

        halo[0][tid + 2] = make_float4(A0, A1, A2, A3);
        if (tid == 0) {
            float4 n4 = make_float4(NEGF, NEGF, NEGF, NEGF);
            halo[0][0] = n4; halo[0][1] = n4; halo[1][0] = n4; halo[1][1] = n4;
        }
        __syncthreads();

        if (inLen >= Tc) {
            for (int jj = 0; jj < 127; ++jj) {
                const int j = 2 * jj;
                FWD_BODY(j,     1, 2, 3, 0, true, true);
                FWD_BODY(j + 1, 3, 0, 1, 2, true, true);
            }
            FWD_BODY(254, 1, 2, 3, 0, true, true);
            FWD_FINAL(3, true);
        } else {
            for (int jj = 0; jj < 127; ++jj) {
                const int j = 2 * jj;
                FWD_BODY(j,     1, 2, 3, 0, (2*j+1 < inLen), (2*j+2 < inLen));
                FWD_BODY(j + 1, 3, 0, 1, 2, (2*j+3 < inLen), (2*j+4 < inLen));
            }
            FWD_BODY(254, 1, 2, 3, 0, (509 < inLen), (510 < inLen));
            FWD_FINAL(3, (511 < inLen));
        }

        float* __restrict__ aOut = g_alpha[b];
        const int sbase = 4 * tid;
        aOut[sbase] = A0; aOut[sbase + 1] = A1; aOut[sbase + 2] = A2; aOut[sbase + 3] = A3;
        if (isLast) aOut[512] = A4;

    } else {
        // per-thread labels for states 4t+1, 4t+3, 4t+5, 4t+7 (clamped)
        const int eb1 = yt[2 * tid];
        const int eb3 = yt[min(2 * tid + 1, Lc - 1)];
        const int eb5 = yt[min(2 * tid + 2, Lc - 1)];
        const int eb7 = yt[min(2 * tid + 3, Lc - 1)];
        const bool skbA = (eb3 != eb1);                       // 4t+3 <= 512 always
        const bool skbB = (tid <= 126) && (eb5 != eb3);       // target 4t+5 <= 512
        const bool skbC = (tid <= 126) && (eb7 != eb5);       // target 4t+7 <= 512

        const int se = 2 * labLen;
        const int sbase = 4 * tid;
        float g0 = (sbase     == se || (labLen > 0 && sbase     == se - 1)) ? 0.f : NEGF;
        float g1 = (sbase + 1 == se || (labLen > 0 && sbase + 1 == se - 1)) ? 0.f : NEGF;
        float g2 = (sbase + 2 == se || (labLen > 0 && sbase + 2 == se - 1)) ? 0.f : NEGF;
        float g3 = (sbase + 3 == se || (labLen > 0 && sbase + 3 == se - 1)) ? 0.f : NEGF;
        float A2 = (512 == se) ? 0.f : NEGF;   // gamma[512]

        lpS[3][tid] = lg2f_(yp[(size_t)1023 * Cc + tid] + EPSF);
        lpS[2][tid] = lg2f_(yp[(size_t)1022 * Cc + tid] + EPSF);
        float pA0 = yp[(size_t)1021 * Cc + tid], pA1 = yp[(size_t)1020 * Cc + tid];
        float pB0 = yp[(size_t)1019 * Cc + tid], pB1 = yp[(size_t)1018 * Cc + tid];
        float pC0 = yp[(size_t)1017 * Cc + tid], pC1 = yp[(size_t)1016 * Cc + tid];

        halo[0][tid] = make_float4(g0, g1, g2, g3);
        __syncthreads();

        if (inLen >= Tc) {
            for (int jj = 0; jj < 128; ++jj) {
                const int j = 2 * jj;
                BWD_BODY(j,     3, 2, 1, 0, true, true);
                BWD_BODY(j + 1, 1, 0, 3, 2, true, true);
            }
        } else {
            for (int jj = 0; jj < 128; ++jj) {
                const int j = 2 * jj;
                BWD_BODY(j,     3, 2, 1, 0, (1023-2*j < inLen), (1022-2*j < inLen));
                BWD_BODY(j + 1, 1, 0, 3, 2, (1021-2*j < inLen), (1020-2*j < inLen));
            }
        }

        float* __restrict__ gOut = g_gamma[b];
        gOut[sbase] = g0; gOut[sbase + 1] = g1; gOut[sbase + 2] = g2; gOut[sbase + 3] = g3;
        if (isLast) gOut[512] = A2;
    }

    // =================== second-arriver inline combine ===================
    __threadfence();        // release our snapshot (every thread fences its own stores)
    __syncthreads();
    if (tid == 0) ticket = atomicAdd(&g_done[b], 1);
    __syncthreads();

    if (ticket == 1) {
        // we arrived second: both snapshots are visible (partner fenced before its atomic)
        const float* __restrict__ a = g_alpha[b];
        const float* __restrict__ g = g_gamma[b];
        const int s0 = tid * 4;
        float c0 = __ldcg(&a[s0])     + __ldcg(&g[s0]);
        float c1 = __ldcg(&a[s0 + 1]) + __ldcg(&g[s0 + 1]);
        float c2 = __ldcg(&a[s0 + 2]) + __ldcg(&g[s0 + 2]);
        float c3 = __ldcg(&a[s0 + 3]) + __ldcg(&g[s0 + 3]);
        float local = lse2f(lse2f(c0, c1), lse2f(c2, c3));
        if (tid == NT - 1) local = lse2f(local, __ldcg(&a[512]) + __ldcg(&g[512]));
        #pragma unroll
        for (int off = 16; off > 0; off >>= 1)
            local = lse2f(local, __shfl_xor_sync(0xffffffffu, local, off));
        if ((tid & 31) == 0) warpRes[tid >> 5] = local;
        __syncthreads();
        if (tid == 0) {
            float r = lse2f(lse2f(warpRes[0], warpRes[1]), lse2f(warpRes[2], warpRes[3]));
            out[b] = -LN2F * r;
            g_done[b] = 0;   // reset counter for the next (graph-replayed) launch
        }
    }
}

extern "C" void kernel_launch(void* const* d_in, const int* in_sizes, int n_in,
                              void* d_out, int out_size) {
    const int*   y_true       = (const int*)d_in[0];
    const float* y_pred       = (const float*)d_in[1];
    const int*   input_length = (const int*)d_in[2];
    const int*   label_length = (const int*)d_in[3];
    float* out = (float*)d_out;

    ctc_fb_kernel<<<2 * Bc, NT>>>(y_true, y_pred, input_length, label_length, out);
}